// round 12
// baseline (speedup 1.0000x reference)
#include <cuda_runtime.h>

#define BATCH        16384
#define NUM_FIELDS   20
#define NUM_FEATURES 100000
#define LATENT_DIM   64

// R7 layout with software-pipelined gather bursts.
// Two samples per warp (one per half-warp); each lane owns 4 of 64 dims ->
// LDG.128 per embedding row. Gathers in 4 groups of 5, double-buffered:
//   load G0; load G1; { consume G_{i-1} || load G_{i+1} }; ...
// => 5-10 loads continuously in flight per lane (never front-batches > 10,
// the measured contention-safe band), no drain bubble between bursts.
__global__ __launch_bounds__(256)
void ffm_kernel(const int* __restrict__ x,
                const float* __restrict__ emb,
                float* __restrict__ out)
{
    const int gwarp = (blockIdx.x * blockDim.x + threadIdx.x) >> 5;
    const int lane  = threadIdx.x & 31;
    const int half  = lane >> 4;          // sample within the warp
    const int lh    = lane & 15;          // lane within half-warp
    const int s     = gwarp * 2 + half;   // batch sample id
    if (s >= BATCH) return;

    // 20 indices per half-warp: lanes 0..15 hold fields 0..15,
    // lanes 0..3 additionally hold fields 16..19.
    const int* xrow = x + s * NUM_FIELDS;
    int xi0 = __ldg(xrow + lh);                                    // fields 0..15
    int xi1 = (lh < NUM_FIELDS - 16) ? __ldg(xrow + 16 + lh) : 0;  // fields 16..19

    // Row pointers for all 20 fields (cheap ALU; addresses ready up front).
    auto row_ptr = [&](int f) -> const float4* {
        int idx;
        if (f < 16) idx = __shfl_sync(0xffffffffu, xi0, f, 16);
        else        idx = __shfl_sync(0xffffffffu, xi1, f - 16, 16);
        return reinterpret_cast<const float4*>(
            emb + ((size_t)f * NUM_FEATURES + (size_t)idx) * LATENT_DIM) + lh;
    };

    float4 sv = make_float4(0.f, 0.f, 0.f, 0.f);
    float  sq = 0.f;

    float4 bufA[5], bufB[5];

    // Prologue: load groups 0 and 1 (fields 0..4, 5..9).
    #pragma unroll
    for (int j = 0; j < 5; ++j) bufA[j] = __ldg(row_ptr(j));
    #pragma unroll
    for (int j = 0; j < 5; ++j) bufB[j] = __ldg(row_ptr(5 + j));
    asm volatile("" ::: "memory");

    // Steady state: consume one group while the next streams in.
    #pragma unroll
    for (int g = 0; g < 2; ++g) {               // g=0: consume A, load fields 10..14 into A
        float4* cons = (g == 0) ? bufA : bufB;  // g=1: consume B, load fields 15..19 into B
        #pragma unroll
        for (int j = 0; j < 5; ++j) {
            // Issue the replacement load first, then consume (load stays ahead).
            const float4 nv = __ldg(row_ptr(10 + g * 5 + j));
            const float4 v  = cons[j];
            cons[j] = nv;
            sv.x += v.x;  sv.y += v.y;  sv.z += v.z;  sv.w += v.w;
            sq = fmaf(v.x, v.x, sq);  sq = fmaf(v.y, v.y, sq);
            sq = fmaf(v.z, v.z, sq);  sq = fmaf(v.w, v.w, sq);
        }
        asm volatile("" ::: "memory");
    }

    // Epilogue: consume the last two groups (fields 10..14 in A, 15..19 in B).
    #pragma unroll
    for (int j = 0; j < 5; ++j) {
        const float4 v = bufA[j];
        sv.x += v.x;  sv.y += v.y;  sv.z += v.z;  sv.w += v.w;
        sq = fmaf(v.x, v.x, sq);  sq = fmaf(v.y, v.y, sq);
        sq = fmaf(v.z, v.z, sq);  sq = fmaf(v.w, v.w, sq);
    }
    #pragma unroll
    for (int j = 0; j < 5; ++j) {
        const float4 v = bufB[j];
        sv.x += v.x;  sv.y += v.y;  sv.z += v.z;  sv.w += v.w;
        sq = fmaf(v.x, v.x, sq);  sq = fmaf(v.y, v.y, sq);
        sq = fmaf(v.z, v.z, sq);  sq = fmaf(v.w, v.w, sq);
    }

    float part = fmaf(sv.x, sv.x, fmaf(sv.y, sv.y,
                 fmaf(sv.z, sv.z, sv.w * sv.w))) - sq;
    int   lin  = xi0 + xi1;

    // Reduce within the 16-lane half-warp.
    #pragma unroll
    for (int o = 8; o > 0; o >>= 1) {
        part += __shfl_xor_sync(0xffffffffu, part, o);
        lin  += __shfl_xor_sync(0xffffffffu, lin,  o);
    }

    if (lh == 0)
        out[s] = (float)lin + 0.5f * part;
}

extern "C" void kernel_launch(void* const* d_in, const int* in_sizes, int n_in,
                              void* d_out, int out_size)
{
    const int*   x   = (const int*)d_in[0];     // (16384, 20) int32
    // d_in[1] = field_indices (arange(20)) — identity, unused
    const float* emb = (const float*)d_in[2];   // (20, 100000, 64) fp32
    float*       out = (float*)d_out;           // (16384,) fp32

    const int threads = 256;                    // 8 warps = 16 samples / block
    const int warps   = (BATCH + 1) / 2;        // 8192 warps
    const int blocks  = (warps * 32 + threads - 1) / threads;  // 1024
    ffm_kernel<<<blocks, threads>>>(x, emb, out);
}